// round 15
// baseline (speedup 1.0000x reference)
#include <cuda_runtime.h>
#include <stdint.h>
#include <math.h>

#define BB 32
#define SS 4096
#define DD 1024
#define OO 1024
#define NBLK 64                // score blocks per batch (SS/64)
#define WIN 96                 // Gaussian window half-width: exp(-96^2/128)=5e-32, negligible
#define INV2SS (1.0f/128.0f)   // 1/(2*STDDEV^2), STDDEV=8
#define KS 16                  // K-splits for epilogue GEMM (2048/128)
#define KT 128                 // K per split
#define OT 64                  // output cols per block
#define WSPLIT 4               // window splits for weighted kernel
#define CH 64                  // floats of D per score chunk
#define NCH (DD / CH)          // 16 chunks

// Scratch (no allocs allowed anywhere)
__device__ float g_score[BB * SS];        // 512 KB
__device__ float g_bmax[BB * NBLK];       // per-score-block max
__device__ float g_bsum[BB * NBLK];       // per-score-block sum of exp(.-bmax)
__device__ float g_wpart[WSPLIT * BB * DD];  // 512 KB weighted partials
__device__ float g_part[KS * BB * OO];    // 2 MB split-K partials

// cp.async helpers ----------------------------------------------------------
__device__ __forceinline__ void cp_async16(void* smem_dst, const void* gmem_src) {
    unsigned sa = (unsigned)__cvta_generic_to_shared(smem_dst);
    asm volatile("cp.async.cg.shared.global [%0], [%1], 16;"
                 :: "r"(sa), "l"(gmem_src));
}
__device__ __forceinline__ void cp_async_commit() {
    asm volatile("cp.async.commit_group;");
}
template <int N>
__device__ __forceinline__ void cp_async_wait() {
    asm volatile("cp.async.wait_group %0;" :: "n"(N));
}

// ---------------------------------------------------------------------------
// Kernel 1: score[b,s] = dot(source[b,s,:], target[b,:]) + block softmax
// partials. grid (S/64, B), 256 threads.
// cp.async (LDGSTS) double-buffered streaming: MLP lives in the LSU queue,
// not registers (R11 ncu: regs=32 capped in-flight loads, DRAM stuck 72.7%).
// Per chunk: stage 64 rows x 256B into smem (4 LDGSTS/thread), then each
// thread (row=tid>>2, q=tid&3) accumulates its 16-float slice of the dot.
// ---------------------------------------------------------------------------
__global__ void __launch_bounds__(256) score_kernel(const float* __restrict__ src,
                                                    const float* __restrict__ tgt) {
    __shared__ float4 st4[DD / 4];        // target row, 4 KB
    __shared__ float4 buf[2][64 * 16];    // 2 x 16 KB stages
    __shared__ float scs[64];             // final 64 row scores
    const int b = blockIdx.y;
    const int tid = threadIdx.x;

    st4[tid] = reinterpret_cast<const float4*>(tgt + (size_t)b * DD)[tid];

    const int row0 = blockIdx.x * 64;
    const float* base = src + ((size_t)b * SS + row0) * DD;

    // stage chunk c (floats [c*CH, c*CH+CH) of all 64 rows) into buf[c&1]
    auto load_chunk = [&](int c) {
        const int s = c & 1;
        #pragma unroll
        for (int j = 0; j < 4; j++) {
            const int e = tid + 256 * j;
            const int r = e >> 4, f = e & 15;
            cp_async16(&buf[s][r * 16 + f],
                       reinterpret_cast<const float4*>(
                           base + (size_t)r * DD + c * CH) + f);
        }
        cp_async_commit();
    };

    load_chunk(0);

    const int row = tid >> 2, q = tid & 3;
    float acc = 0.f;

    #pragma unroll
    for (int c = 0; c < NCH; c++) {
        if (c + 1 < NCH) {
            load_chunk(c + 1);
            cp_async_wait<1>();      // chunk c retired
        } else {
            cp_async_wait<0>();
        }
        __syncthreads();
        const int s = c & 1;
        #pragma unroll
        for (int j = 0; j < 4; j++) {
            float4 v = buf[s][row * 16 + q * 4 + j];
            float4 t = st4[c * 16 + q * 4 + j];       // broadcast within warp
            acc += v.x * t.x + v.y * t.y + v.z * t.z + v.w * t.w;
        }
        __syncthreads();
    }

    // finish the dot: 4 threads per row -> 2 shfl steps
    acc += __shfl_xor_sync(0xffffffffu, acc, 1);
    acc += __shfl_xor_sync(0xffffffffu, acc, 2);
    if (q == 0) {
        g_score[b * SS + row0 + row] = acc;
        scs[row] = acc;
    }
    __syncthreads();

    // block-level softmax partials over the 64 scores (one warp)
    if (tid < 32) {
        const float x0 = scs[tid], x1 = scs[tid + 32];
        float m = fmaxf(x0, x1);
        #pragma unroll
        for (int off = 16; off; off >>= 1)
            m = fmaxf(m, __shfl_xor_sync(0xffffffffu, m, off));
        float s = expf(x0 - m) + expf(x1 - m);
        #pragma unroll
        for (int off = 16; off; off >>= 1)
            s += __shfl_xor_sync(0xffffffffu, s, off);
        if (tid == 0) {
            g_bmax[b * NBLK + blockIdx.x] = m;
            g_bsum[b * NBLK + blockIdx.x] = s;
        }
    }
}

// ---------------------------------------------------------------------------
// Kernel 2: weighted partials, window split 4 ways, with INLINE softmax
// stats merge. grid (D/256, B, WSPLIT), 256 threads.
// ---------------------------------------------------------------------------
__global__ void __launch_bounds__(256) weighted_kernel(const float* __restrict__ src,
                                                       const int* __restrict__ pos) {
    __shared__ float wc[64];          // this split's coefficients (<=49)
    __shared__ float s_m, s_s;
    const int b = blockIdx.y;
    const int z = blockIdx.z;
    const int tid = threadIdx.x;

    // inline stats merge over the 64 score blocks of this batch
    if (tid < 32) {
        const float m0 = g_bmax[b * NBLK + tid];
        const float m1 = g_bmax[b * NBLK + tid + 32];
        const float s0 = g_bsum[b * NBLK + tid];
        const float s1 = g_bsum[b * NBLK + tid + 32];
        float m = fmaxf(m0, m1);
        #pragma unroll
        for (int off = 16; off; off >>= 1)
            m = fmaxf(m, __shfl_xor_sync(0xffffffffu, m, off));
        float s = s0 * expf(m0 - m) + s1 * expf(m1 - m);
        #pragma unroll
        for (int off = 16; off; off >>= 1)
            s += __shfl_xor_sync(0xffffffffu, s, off);
        if (tid == 0) { s_m = m; s_s = s; }
    }
    __syncthreads();

    const int p = pos[b];
    const int s0w = max(0, p - WIN);
    const int s1w = min(SS - 1, p + WIN);
    const int n = s1w - s0w + 1;
    const int cl = (n + WSPLIT - 1) / WSPLIT;      // chunk length
    const int c0 = z * cl;                          // chunk start (rel)
    const int cn = min(cl, n - c0);                 // chunk rows (may be <=0)

    if (tid < cl && tid < cn) {
        const int s = s0w + c0 + tid;
        const float rel = (float)(s - p);
        wc[tid] = expf(g_score[b * SS + s] - s_m) * (1.0f / s_s)
                * expf(-rel * rel * INV2SS);
    }
    __syncthreads();

    const int d = blockIdx.x * 256 + tid;
    const float* sp = src + ((size_t)b * SS + s0w + c0) * DD + d;
    float acc = 0.f;
    for (int i = 0; i < cn; i++)
        acc += wc[i] * sp[(size_t)i * DD];   // coalesced 1KB rows
    g_wpart[((size_t)z * BB + b) * DD + d] = acc;
}

// ---------------------------------------------------------------------------
// Kernel 3: split-K partial GEMM (R8 measured-best shape).
// C=[32,2048] (concat of target and sum-of-wpart), W=[2048,1024].
// grid (16 otiles, 16 ks) = 256 blocks. Scalar broadcast compute loop.
// ---------------------------------------------------------------------------
__global__ void __launch_bounds__(256) out_partial(const float* __restrict__ tgt,
                                                   const float* __restrict__ Wm) {
    __shared__ float sC[BB][KT];       // 16 KB
    __shared__ float sW[KT][OT];       // 32 KB
    const int tid = threadIdx.x;
    const int obase = blockIdx.x * OT;
    const int ks = blockIdx.y;
    const int kg0 = ks * KT;
    const int koff = kg0 & (DD - 1);

    float4* sC4 = reinterpret_cast<float4*>(&sC[0][0]);
    if (kg0 < DD) {
        // target half: 1024 float4, 4 per thread
        #pragma unroll
        for (int j = 0; j < 4; j++) {
            const int e = tid + 256 * j;           // e = row*32 + c4
            sC4[e] = reinterpret_cast<const float4*>(
                tgt + (e >> 5) * DD + koff)[e & 31];
        }
    } else {
        // weighted half: sum 4 window partials inline (16 loads per thread)
        const float4* wp4 = reinterpret_cast<const float4*>(g_wpart);
        #pragma unroll
        for (int j = 0; j < 4; j++) {
            const int e = tid + 256 * j;           // e = row*32 + c4
            const size_t idx = (size_t)(e >> 5) * (DD / 4) + (koff >> 2) + (e & 31);
            float4 v0 = wp4[idx];
            float4 v1 = wp4[idx + 1 * (BB * DD / 4)];
            float4 v2 = wp4[idx + 2 * (BB * DD / 4)];
            float4 v3 = wp4[idx + 3 * (BB * DD / 4)];
            float4 s;
            s.x = (v0.x + v1.x) + (v2.x + v3.x);
            s.y = (v0.y + v1.y) + (v2.y + v3.y);
            s.z = (v0.z + v1.z) + (v2.z + v3.z);
            s.w = (v0.w + v1.w) + (v2.w + v3.w);
            sC4[e] = s;
        }
    }
    float4* sW4 = reinterpret_cast<float4*>(&sW[0][0]);
    #pragma unroll
    for (int j = 0; j < 8; j++) {
        const int e = tid + 256 * j;           // e = k*16 + c4
        sW4[e] = reinterpret_cast<const float4*>(
            Wm + (size_t)(kg0 + (e >> 4)) * OO + obase)[e & 15];
    }
    __syncthreads();

    const int oc = tid & 63;       // consecutive within warp -> conflict-free sW
    const int bq = tid >> 6;       // 0..3, each owns 8 batches
    float acc[8];
    #pragma unroll
    for (int i = 0; i < 8; i++) acc[i] = 0.f;

    #pragma unroll 4
    for (int k = 0; k < KT; k++) {
        const float w = sW[k][oc];
        #pragma unroll
        for (int i = 0; i < 8; i++)
            acc[i] += sC[bq * 8 + i][k] * w;   // broadcast reads
    }

    #pragma unroll
    for (int i = 0; i < 8; i++)
        g_part[((size_t)ks * BB + bq * 8 + i) * OO + obase + oc] = acc[i];
}

// ---------------------------------------------------------------------------
// Kernel 4: out[b,o] = tanh(sum_ks part[ks,b,o]). Scalar per thread:
// 32768 threads / 128 blocks, coalesced stride-BB*OO plane loads.
// ---------------------------------------------------------------------------
__global__ void __launch_bounds__(256) out_reduce(float* __restrict__ out) {
    const int idx = blockIdx.x * 256 + threadIdx.x;   // b*OO + o
    float s = 0.f;
    #pragma unroll
    for (int ks = 0; ks < KS; ks++)
        s += g_part[(size_t)ks * (BB * OO) + idx];
    out[idx] = tanhf(s);
}

// ---------------------------------------------------------------------------
extern "C" void kernel_launch(void* const* d_in, const int* in_sizes, int n_in,
                              void* d_out, int out_size) {
    const float* src = (const float*)d_in[0];   // [B,S,D]
    const float* tgt = (const float*)d_in[1];   // [B,D]
    const int*   pos = (const int*)d_in[2];     // [B]
    const float* Wm  = (const float*)d_in[3];   // [2D,O]
    float* out = (float*)d_out;                 // [B,O]

    score_kernel<<<dim3(SS / 64, BB), 256>>>(src, tgt);
    weighted_kernel<<<dim3(DD / 256, BB, WSPLIT), 256>>>(src, pos);
    out_partial<<<dim3(OO / OT, KS), 256>>>(tgt, Wm);
    out_reduce<<<BB * OO / 256, 256>>>(out);
}

// round 16
// speedup vs baseline: 1.1975x; 1.1975x over previous
#include <cuda_runtime.h>
#include <stdint.h>
#include <math.h>

#define BB 32
#define SS 4096
#define DD 1024
#define OO 1024
#define NBLK 64                // score blocks per batch (SS/64)
#define WIN 96                 // Gaussian window half-width: exp(-96^2/128)=5e-32, negligible
#define INV2SS (1.0f/128.0f)   // 1/(2*STDDEV^2), STDDEV=8
#define KS 16                  // K-splits for epilogue GEMM (2048/128)
#define KT 128                 // K per split
#define OT 32                  // output cols per block (32 -> 512 blocks, 32KB smem)
#define WSPLIT 4               // window splits for weighted kernel

// Scratch (no allocs allowed anywhere)
__device__ float g_score[BB * SS];        // 512 KB
__device__ float g_bmax[BB * NBLK];       // per-score-block max
__device__ float g_bsum[BB * NBLK];       // per-score-block sum of exp(.-bmax)
__device__ float g_wpart[WSPLIT * BB * DD];  // 512 KB weighted partials
__device__ float g_part[KS * BB * OO];    // 2 MB split-K partials

// ---------------------------------------------------------------------------
// Kernel 1: score[b,s] = dot(source[b,s,:], target[b,:]) + block softmax
// partials. grid (S/64, B), 256 threads, 8 warps x 8 rows.
// R8 proven shape (93.9us, DRAM 72.7%): no shfl on the load path — lane
// partials go to smem, one block-wide pass reduces 64 rows at the end.
// LOCKED: R12 interleave was neutral, R15 cp.async regressed. Do not touch.
// ---------------------------------------------------------------------------
__global__ void __launch_bounds__(256) score_kernel(const float* __restrict__ src,
                                                    const float* __restrict__ tgt) {
    __shared__ float4 st[DD / 4];     // target row, 4 KB
    __shared__ float sc2[64 * 33];    // per-(row,lane) partials, padded, 8.25 KB
    __shared__ float scs[64];         // final 64 row scores
    const int b = blockIdx.y;
    const int tid = threadIdx.x;

    st[tid] = reinterpret_cast<const float4*>(tgt + (size_t)b * DD)[tid];
    __syncthreads();

    const int warp = tid >> 5, lane = tid & 31;
    const int row0 = blockIdx.x * 64 + warp * 8;

    #pragma unroll
    for (int i = 0; i < 8; i++) {
        const float4* s4 = reinterpret_cast<const float4*>(
            src + ((size_t)b * SS + row0 + i) * DD);
        float4 a = make_float4(0.f, 0.f, 0.f, 0.f);
        #pragma unroll
        for (int k = 0; k < 8; k++) {
            float4 v = __ldcs(s4 + lane + 32 * k);
            float4 t = st[lane + 32 * k];
            a.x += v.x * t.x; a.y += v.y * t.y;
            a.z += v.z * t.z; a.w += v.w * t.w;
        }
        sc2[(warp * 8 + i) * 33 + lane] = (a.x + a.y) + (a.z + a.w);
    }
    __syncthreads();

    // reduce 64 rows: 4 threads/row, each sums 8 lanes, then 2 shfl steps.
    {
        const int row = tid >> 2, q = tid & 3;
        float s = 0.f;
        #pragma unroll
        for (int j = 0; j < 8; j++) s += sc2[row * 33 + q * 8 + j];
        s += __shfl_xor_sync(0xffffffffu, s, 1);
        s += __shfl_xor_sync(0xffffffffu, s, 2);
        if (q == 0) {
            g_score[b * SS + blockIdx.x * 64 + row] = s;
            scs[row] = s;
        }
    }
    __syncthreads();

    // block-level softmax partials over the 64 scores (one warp)
    if (tid < 32) {
        const float x0 = scs[tid], x1 = scs[tid + 32];
        float m = fmaxf(x0, x1);
        #pragma unroll
        for (int off = 16; off; off >>= 1)
            m = fmaxf(m, __shfl_xor_sync(0xffffffffu, m, off));
        float s = expf(x0 - m) + expf(x1 - m);
        #pragma unroll
        for (int off = 16; off; off >>= 1)
            s += __shfl_xor_sync(0xffffffffu, s, off);
        if (tid == 0) {
            g_bmax[b * NBLK + blockIdx.x] = m;
            g_bsum[b * NBLK + blockIdx.x] = s;
        }
    }
}

// ---------------------------------------------------------------------------
// Kernel 2: weighted partials, window split 4 ways, with INLINE softmax
// stats merge. grid (D/256, B, WSPLIT), 256 threads.
// ---------------------------------------------------------------------------
__global__ void __launch_bounds__(256) weighted_kernel(const float* __restrict__ src,
                                                       const int* __restrict__ pos) {
    __shared__ float wc[64];          // this split's coefficients (<=49)
    __shared__ float s_m, s_s;
    const int b = blockIdx.y;
    const int z = blockIdx.z;
    const int tid = threadIdx.x;

    // inline stats merge over the 64 score blocks of this batch
    if (tid < 32) {
        const float m0 = g_bmax[b * NBLK + tid];
        const float m1 = g_bmax[b * NBLK + tid + 32];
        const float s0 = g_bsum[b * NBLK + tid];
        const float s1 = g_bsum[b * NBLK + tid + 32];
        float m = fmaxf(m0, m1);
        #pragma unroll
        for (int off = 16; off; off >>= 1)
            m = fmaxf(m, __shfl_xor_sync(0xffffffffu, m, off));
        float s = s0 * expf(m0 - m) + s1 * expf(m1 - m);
        #pragma unroll
        for (int off = 16; off; off >>= 1)
            s += __shfl_xor_sync(0xffffffffu, s, off);
        if (tid == 0) { s_m = m; s_s = s; }
    }
    __syncthreads();

    const int p = pos[b];
    const int s0w = max(0, p - WIN);
    const int s1w = min(SS - 1, p + WIN);
    const int n = s1w - s0w + 1;
    const int cl = (n + WSPLIT - 1) / WSPLIT;      // chunk length
    const int c0 = z * cl;                          // chunk start (rel)
    const int cn = min(cl, n - c0);                 // chunk rows (may be <=0)

    if (tid < cl && tid < cn) {
        const int s = s0w + c0 + tid;
        const float rel = (float)(s - p);
        wc[tid] = expf(g_score[b * SS + s] - s_m) * (1.0f / s_s)
                * expf(-rel * rel * INV2SS);
    }
    __syncthreads();

    const int d = blockIdx.x * 256 + tid;
    const float* sp = src + ((size_t)b * SS + s0w + c0) * DD + d;
    float acc = 0.f;
    for (int i = 0; i < cn; i++)
        acc += wc[i] * sp[(size_t)i * DD];   // coalesced 1KB rows
    g_wpart[((size_t)z * BB + b) * DD + d] = acc;
}

// ---------------------------------------------------------------------------
// Kernel 3: split-K partial GEMM. C=[32,2048] (concat of target and
// sum-of-wpart), W=[2048,1024]. grid (32 otiles, 16 ks) = 512 blocks,
// 32 KB smem (OT=32): 2x blocks vs R8, same scalar broadcast loop shape.
// Thread (oc=tid&31, bg=tid>>5): 4 batches x 1 col.
// ---------------------------------------------------------------------------
__global__ void __launch_bounds__(256) out_partial(const float* __restrict__ tgt,
                                                   const float* __restrict__ Wm) {
    __shared__ float sC[BB][KT];       // 16 KB
    __shared__ float sW[KT][OT];       // 16 KB
    const int tid = threadIdx.x;
    const int obase = blockIdx.x * OT;
    const int ks = blockIdx.y;
    const int kg0 = ks * KT;
    const int koff = kg0 & (DD - 1);

    float4* sC4 = reinterpret_cast<float4*>(&sC[0][0]);
    if (kg0 < DD) {
        // target half: 1024 float4, 4 per thread
        #pragma unroll
        for (int j = 0; j < 4; j++) {
            const int e = tid + 256 * j;           // e = row*32 + c4
            sC4[e] = reinterpret_cast<const float4*>(
                tgt + (e >> 5) * DD + koff)[e & 31];
        }
    } else {
        // weighted half: sum 4 window partials inline (16 loads per thread)
        const float4* wp4 = reinterpret_cast<const float4*>(g_wpart);
        #pragma unroll
        for (int j = 0; j < 4; j++) {
            const int e = tid + 256 * j;           // e = row*32 + c4
            const size_t idx = (size_t)(e >> 5) * (DD / 4) + (koff >> 2) + (e & 31);
            float4 v0 = wp4[idx];
            float4 v1 = wp4[idx + 1 * (BB * DD / 4)];
            float4 v2 = wp4[idx + 2 * (BB * DD / 4)];
            float4 v3 = wp4[idx + 3 * (BB * DD / 4)];
            float4 s;
            s.x = (v0.x + v1.x) + (v2.x + v3.x);
            s.y = (v0.y + v1.y) + (v2.y + v3.y);
            s.z = (v0.z + v1.z) + (v2.z + v3.z);
            s.w = (v0.w + v1.w) + (v2.w + v3.w);
            sC4[e] = s;
        }
    }
    // stage W slice [128][32]: 1024 float4, 4 per thread
    float4* sW4 = reinterpret_cast<float4*>(&sW[0][0]);
    #pragma unroll
    for (int j = 0; j < 4; j++) {
        const int e = tid + 256 * j;           // e = k*8 + c4
        sW4[e] = reinterpret_cast<const float4*>(
            Wm + (size_t)(kg0 + (e >> 3)) * OO + obase)[e & 7];
    }
    __syncthreads();

    const int oc = tid & 31;       // consecutive within warp -> conflict-free sW
    const int bg = tid >> 5;       // 0..7, each owns 4 batches
    float acc[4];
    #pragma unroll
    for (int i = 0; i < 4; i++) acc[i] = 0.f;

    #pragma unroll 8
    for (int k = 0; k < KT; k++) {
        const float w = sW[k][oc];
        #pragma unroll
        for (int i = 0; i < 4; i++)
            acc[i] += sC[bg * 4 + i][k] * w;   // broadcast reads
    }

    #pragma unroll
    for (int i = 0; i < 4; i++)
        g_part[((size_t)ks * BB + bg * 4 + i) * OO + obase + oc] = acc[i];
}

// ---------------------------------------------------------------------------
// Kernel 4: out[b,o] = tanh(sum_ks part[ks,b,o]). Scalar per thread:
// 32768 threads / 128 blocks, coalesced stride-BB*OO plane loads.
// ---------------------------------------------------------------------------
__global__ void __launch_bounds__(256) out_reduce(float* __restrict__ out) {
    const int idx = blockIdx.x * 256 + threadIdx.x;   // b*OO + o
    float s = 0.f;
    #pragma unroll
    for (int ks = 0; ks < KS; ks++)
        s += g_part[(size_t)ks * (BB * OO) + idx];
    out[idx] = tanhf(s);
}

// ---------------------------------------------------------------------------
extern "C" void kernel_launch(void* const* d_in, const int* in_sizes, int n_in,
                              void* d_out, int out_size) {
    const float* src = (const float*)d_in[0];   // [B,S,D]
    const float* tgt = (const float*)d_in[1];   // [B,D]
    const int*   pos = (const int*)d_in[2];     // [B]
    const float* Wm  = (const float*)d_in[3];   // [2D,O]
    float* out = (float*)d_out;                 // [B,O]

    score_kernel<<<dim3(SS / 64, BB), 256>>>(src, tgt);
    weighted_kernel<<<dim3(DD / 256, BB, WSPLIT), 256>>>(src, pos);
    out_partial<<<dim3(OO / OT, KS), 256>>>(tgt, Wm);
    out_reduce<<<BB * OO / 256, 256>>>(out);
}